// round 2
// baseline (speedup 1.0000x reference)
#include <cuda_runtime.h>

// ChamferLoss: B=4, N=M=8192, D=3
// dist(a,b) = a^2 + (b^2 - 2 a.b); min over b of (b^2 - 2 a.b), add a^2 after.
// chamfer = (sum of all 2*B*N per-point mins) / (B*N)

#define TPB   256
#define TS    2048
#define NPTS  8192
#define NB    4
#define CHUNKS (NPTS / TPB)        // 32
#define NPART  (CHUNKS * NB * 2)   // 256 partials

__device__ float g_partials[NPART];

__global__ __launch_bounds__(TPB) void chamfer_min_kernel(
    const float* __restrict__ p1, const float* __restrict__ p2)
{
    const int dir = blockIdx.z;           // 0: p1->p2, 1: p2->p1
    const int b   = blockIdx.y;
    const float* __restrict__ q = (dir == 0) ? p1 : p2;
    const float* __restrict__ d = (dir == 0) ? p2 : p1;
    q += (size_t)b * NPTS * 3;
    d += (size_t)b * NPTS * 3;

    const int i = blockIdx.x * TPB + threadIdx.x;   // query point index
    const float ax = q[3 * i + 0];
    const float ay = q[3 * i + 1];
    const float az = q[3 * i + 2];
    const float a2  = ax * ax + ay * ay + az * az;
    const float m2x = -2.0f * ax;
    const float m2y = -2.0f * ay;
    const float m2z = -2.0f * az;

    float best = 3.4e38f;

    __shared__ float4 tile[TS];          // 32 KB
    __shared__ float  red[TPB / 32];

    for (int t = 0; t < NPTS; t += TS) {
        __syncthreads();
        // cooperative pack: (bx,by,bz,b2)
        #pragma unroll
        for (int k = threadIdx.x; k < TS; k += TPB) {
            const float bx = d[3 * (t + k) + 0];
            const float by = d[3 * (t + k) + 1];
            const float bz = d[3 * (t + k) + 2];
            tile[k] = make_float4(bx, by, bz, bx * bx + by * by + bz * bz);
        }
        __syncthreads();

        #pragma unroll 8
        for (int j = 0; j < TS; ++j) {
            const float4 v = tile[j];
            float dd = fmaf(m2z, v.z, v.w);
            dd = fmaf(m2y, v.y, dd);
            dd = fmaf(m2x, v.x, dd);
            best = fminf(best, dd);
        }
    }

    float val = a2 + best;               // = min squared distance for point i

    // block reduction (deterministic)
    #pragma unroll
    for (int o = 16; o > 0; o >>= 1)
        val += __shfl_down_sync(0xffffffffu, val, o);
    if ((threadIdx.x & 31) == 0) red[threadIdx.x >> 5] = val;
    __syncthreads();
    if (threadIdx.x < TPB / 32) {
        val = red[threadIdx.x];
        #pragma unroll
        for (int o = (TPB / 64); o > 0; o >>= 1)
            val += __shfl_down_sync(0xffu, val, o);
        if (threadIdx.x == 0)
            g_partials[(dir * NB + b) * CHUNKS + blockIdx.x] = val;
    }
}

__global__ void chamfer_finalize_kernel(float* __restrict__ out)
{
    __shared__ float red[NPART / 32];
    float v = g_partials[threadIdx.x];
    #pragma unroll
    for (int o = 16; o > 0; o >>= 1)
        v += __shfl_down_sync(0xffffffffu, v, o);
    if ((threadIdx.x & 31) == 0) red[threadIdx.x >> 5] = v;
    __syncthreads();
    if (threadIdx.x < NPART / 32) {
        v = red[threadIdx.x];
        #pragma unroll
        for (int o = (NPART / 64); o > 0; o >>= 1)
            v += __shfl_down_sync(0xffu, v, o);
        if (threadIdx.x == 0)
            out[0] = v * (1.0f / (float)(NB * NPTS));
    }
}

extern "C" void kernel_launch(void* const* d_in, const int* in_sizes, int n_in,
                              void* d_out, int out_size)
{
    const float* p1 = (const float*)d_in[0];
    const float* p2 = (const float*)d_in[1];
    float* out = (float*)d_out;

    dim3 grid(CHUNKS, NB, 2);
    chamfer_min_kernel<<<grid, TPB>>>(p1, p2);
    chamfer_finalize_kernel<<<1, NPART>>>(out);
}

// round 3
// speedup vs baseline: 1.4387x; 1.4387x over previous
#include <cuda_runtime.h>

// ChamferLoss: B=4, N=M=8192, D=3
// dist(a,b) = a^2 + (b^2 - 2 a.b). min_b distributes over the a^2 constant.
// Packed f32x2 FFMA over candidate pairs; 2 queries per thread.

#define TPB    256
#define TS     2048                 // candidates per shared tile
#define PAIRS  (TS / 2)             // 1024 pairs
#define NPTS   8192
#define NB     4
#define QPT    2                    // queries per thread
#define CHUNKS (NPTS / (TPB * QPT)) // 16 blocks per (dir,b)
#define NPART  (CHUNKS * NB * 2)    // 128 partials

__device__ float g_partials[NPART];

typedef unsigned long long u64;

__device__ __forceinline__ u64 ffma2(u64 a, u64 b, u64 c) {
    u64 d;
    asm("fma.rn.f32x2 %0, %1, %2, %3;" : "=l"(d) : "l"(a), "l"(b), "l"(c));
    return d;
}
__device__ __forceinline__ u64 pack2(float lo, float hi) {
    u64 d;
    asm("mov.b64 %0, {%1, %2};" : "=l"(d) : "f"(lo), "f"(hi));
    return d;
}
__device__ __forceinline__ void unpack2(u64 v, float& lo, float& hi) {
    asm("mov.b64 {%0, %1}, %2;" : "=f"(lo), "=f"(hi) : "l"(v));
}

__global__ __launch_bounds__(TPB, 1) void chamfer_min_kernel(
    const float* __restrict__ p1, const float* __restrict__ p2)
{
    const int dir = blockIdx.z;           // 0: p1->p2, 1: p2->p1
    const int b   = blockIdx.y;
    const float* __restrict__ q = (dir == 0) ? p1 : p2;
    const float* __restrict__ d = (dir == 0) ? p2 : p1;
    q += (size_t)b * NPTS * 3;
    d += (size_t)b * NPTS * 3;

    // two query points per thread
    const int qbase = blockIdx.x * (TPB * QPT);
    const int i0 = qbase + threadIdx.x;
    const int i1 = qbase + TPB + threadIdx.x;

    const float ax0 = q[3 * i0 + 0], ay0 = q[3 * i0 + 1], az0 = q[3 * i0 + 2];
    const float ax1 = q[3 * i1 + 0], ay1 = q[3 * i1 + 1], az1 = q[3 * i1 + 2];
    const float a2_0 = ax0 * ax0 + ay0 * ay0 + az0 * az0;
    const float a2_1 = ax1 * ax1 + ay1 * ay1 + az1 * az1;

    // packed (-2*coef) broadcast into both f32x2 halves
    const u64 c0x = pack2(-2.0f * ax0, -2.0f * ax0);
    const u64 c0y = pack2(-2.0f * ay0, -2.0f * ay0);
    const u64 c0z = pack2(-2.0f * az0, -2.0f * az0);
    const u64 c1x = pack2(-2.0f * ax1, -2.0f * ax1);
    const u64 c1y = pack2(-2.0f * ay1, -2.0f * ay1);
    const u64 c1z = pack2(-2.0f * az1, -2.0f * az1);

    float b0e = 3.4e38f, b0o = 3.4e38f;   // query0: even/odd-candidate bests
    float b1e = 3.4e38f, b1o = 3.4e38f;

    // pair-interleaved packed tiles:
    //   sA[j] = (x_{2j}|x_{2j+1}, y_{2j}|y_{2j+1})
    //   sB[j] = (z_{2j}|z_{2j+1}, b2_{2j}|b2_{2j+1})
    __shared__ ulonglong2 sA[PAIRS];
    __shared__ ulonglong2 sB[PAIRS];
    __shared__ float red[TPB / 32];

    for (int t = 0; t < NPTS; t += TS) {
        __syncthreads();
        #pragma unroll
        for (int p = threadIdx.x; p < PAIRS; p += TPB) {
            const float* src = d + 3 * (t + 2 * p);   // 6 consecutive floats, 8B-aligned
            const float2 f0 = *(const float2*)(src + 0);   // x0 y0
            const float2 f1 = *(const float2*)(src + 2);   // z0 x1
            const float2 f2 = *(const float2*)(src + 4);   // y1 z1
            const float w0 = f0.x * f0.x + f0.y * f0.y + f1.x * f1.x;
            const float w1 = f1.y * f1.y + f2.x * f2.x + f2.y * f2.y;
            sA[p] = make_ulonglong2(pack2(f0.x, f1.y), pack2(f0.y, f2.x));
            sB[p] = make_ulonglong2(pack2(f1.x, f2.y), pack2(w0, w1));
        }
        __syncthreads();

        #pragma unroll 4
        for (int j = 0; j < PAIRS; ++j) {
            const ulonglong2 A = sA[j];     // (xx, yy)
            const ulonglong2 Bv = sB[j];    // (zz, ww)
            u64 t0 = ffma2(c0z, Bv.x, Bv.y);
            u64 t1 = ffma2(c1z, Bv.x, Bv.y);
            t0 = ffma2(c0y, A.y, t0);
            t1 = ffma2(c1y, A.y, t1);
            t0 = ffma2(c0x, A.x, t0);
            t1 = ffma2(c1x, A.x, t1);
            float lo, hi;
            unpack2(t0, lo, hi);
            b0e = fminf(b0e, lo); b0o = fminf(b0o, hi);
            unpack2(t1, lo, hi);
            b1e = fminf(b1e, lo); b1o = fminf(b1o, hi);
        }
    }

    // per-thread sum of the two query mins
    float val = (a2_0 + fminf(b0e, b0o)) + (a2_1 + fminf(b1e, b1o));

    // deterministic block reduction
    #pragma unroll
    for (int o = 16; o > 0; o >>= 1)
        val += __shfl_down_sync(0xffffffffu, val, o);
    if ((threadIdx.x & 31) == 0) red[threadIdx.x >> 5] = val;
    __syncthreads();
    if (threadIdx.x < TPB / 32) {
        val = red[threadIdx.x];
        #pragma unroll
        for (int o = (TPB / 64); o > 0; o >>= 1)
            val += __shfl_down_sync(0xffu, val, o);
        if (threadIdx.x == 0)
            g_partials[(dir * NB + b) * CHUNKS + blockIdx.x] = val;
    }
}

__global__ void chamfer_finalize_kernel(float* __restrict__ out)
{
    __shared__ float red[NPART / 32];
    float v = g_partials[threadIdx.x];
    #pragma unroll
    for (int o = 16; o > 0; o >>= 1)
        v += __shfl_down_sync(0xffffffffu, v, o);
    if ((threadIdx.x & 31) == 0) red[threadIdx.x >> 5] = v;
    __syncthreads();
    if (threadIdx.x < NPART / 32) {
        v = red[threadIdx.x];
        #pragma unroll
        for (int o = (NPART / 64); o > 0; o >>= 1)
            v += __shfl_down_sync(0xffu, v, o);
        if (threadIdx.x == 0)
            out[0] = v * (1.0f / (float)(NB * NPTS));
    }
}

extern "C" void kernel_launch(void* const* d_in, const int* in_sizes, int n_in,
                              void* d_out, int out_size)
{
    const float* p1 = (const float*)d_in[0];
    const float* p2 = (const float*)d_in[1];
    float* out = (float*)d_out;

    dim3 grid(CHUNKS, NB, 2);
    chamfer_min_kernel<<<grid, TPB>>>(p1, p2);
    chamfer_finalize_kernel<<<1, NPART>>>(out);
}

// round 5
// speedup vs baseline: 1.8025x; 1.2529x over previous
#include <cuda_runtime.h>

// ChamferLoss: B=4, N=M=8192, D=3
// dist(a,b) = a^2 + (b^2 - 2 a.b); min_b distributes over constant a^2.
// f32x2 packed FFMA over candidate pairs, 4 queries/thread, candidate dim
// split 4-ways across blocks; partial mins combined in finalize kernels.

#define TPB    256
#define QPT    4
#define NPTS   8192
#define NB     4
#define NSPLIT 4
#define CANDS  (NPTS / NSPLIT)      // 2048 candidates per block
#define PAIRS  (CANDS / 2)          // 1024
#define QPB    (TPB * QPT)          // 1024 queries per block
#define CHUNKS (NPTS / QPB)         // 8
#define NQSLOT (2 * NB * NPTS)      // 65536 (dir,b,q) slots
#define F1BLK  64

__device__ float4 g_pm4[NQSLOT];    // per (dir,b,query): min per split (a^2 folded in)
__device__ float  g_part[F1BLK];

typedef unsigned long long u64;

__device__ __forceinline__ u64 ffma2(u64 a, u64 b, u64 c) {
    u64 d;
    asm("fma.rn.f32x2 %0, %1, %2, %3;" : "=l"(d) : "l"(a), "l"(b), "l"(c));
    return d;
}
__device__ __forceinline__ u64 pack2(float lo, float hi) {
    u64 d;
    asm("mov.b64 %0, {%1, %2};" : "=l"(d) : "f"(lo), "f"(hi));
    return d;
}
__device__ __forceinline__ void unpack2(u64 v, float& lo, float& hi) {
    asm("mov.b64 {%0, %1}, %2;" : "=f"(lo), "=f"(hi) : "l"(v));
}

__global__ __launch_bounds__(TPB, 2) void chamfer_min_kernel(
    const float* __restrict__ p1, const float* __restrict__ p2)
{
    const int dir   = blockIdx.z & 1;       // 0: p1->p2, 1: p2->p1
    const int split = blockIdx.z >> 1;      // candidate quarter
    const int b     = blockIdx.y;
    const float* __restrict__ q = (dir == 0) ? p1 : p2;
    const float* __restrict__ d = (dir == 0) ? p2 : p1;
    q += (size_t)b * NPTS * 3;
    d += (size_t)b * NPTS * 3 + (size_t)split * CANDS * 3;

    const int qbase = blockIdx.x * QPB;

    // 4 query points per thread
    int   qi[QPT];
    float a2[QPT];
    u64   cx[QPT], cy[QPT], cz[QPT];
    #pragma unroll
    for (int k = 0; k < QPT; ++k) {
        const int i = qbase + k * TPB + threadIdx.x;
        qi[k] = i;
        const float ax = q[3 * i + 0], ay = q[3 * i + 1], az = q[3 * i + 2];
        a2[k] = ax * ax + ay * ay + az * az;
        cx[k] = pack2(-2.0f * ax, -2.0f * ax);
        cy[k] = pack2(-2.0f * ay, -2.0f * ay);
        cz[k] = pack2(-2.0f * az, -2.0f * az);
    }

    // pair-interleaved packed tiles:
    //  sA[j] = (x_{2j}|x_{2j+1}, y_{2j}|y_{2j+1})
    //  sB[j] = (z_{2j}|z_{2j+1}, b2_{2j}|b2_{2j+1})
    __shared__ ulonglong2 sA[PAIRS];
    __shared__ ulonglong2 sB[PAIRS];

    #pragma unroll
    for (int p = threadIdx.x; p < PAIRS; p += TPB) {
        const float* src = d + 6 * p;               // 6 floats, 8B aligned
        const float2 f0 = *(const float2*)(src + 0);   // x0 y0
        const float2 f1 = *(const float2*)(src + 2);   // z0 x1
        const float2 f2 = *(const float2*)(src + 4);   // y1 z1
        const float w0 = f0.x * f0.x + f0.y * f0.y + f1.x * f1.x;
        const float w1 = f1.y * f1.y + f2.x * f2.x + f2.y * f2.y;
        sA[p] = make_ulonglong2(pack2(f0.x, f1.y), pack2(f0.y, f2.x));
        sB[p] = make_ulonglong2(pack2(f1.x, f2.y), pack2(w0, w1));
    }
    __syncthreads();

    float be[QPT], bo[QPT];
    #pragma unroll
    for (int k = 0; k < QPT; ++k) { be[k] = 3.4e38f; bo[k] = 3.4e38f; }

    #pragma unroll 4
    for (int j = 0; j < PAIRS; ++j) {
        const ulonglong2 A  = sA[j];    // (xx, yy)
        const ulonglong2 Bv = sB[j];    // (zz, ww)
        u64 t[QPT];
        #pragma unroll
        for (int k = 0; k < QPT; ++k) t[k] = ffma2(cz[k], Bv.x, Bv.y);
        #pragma unroll
        for (int k = 0; k < QPT; ++k) t[k] = ffma2(cy[k], A.y, t[k]);
        #pragma unroll
        for (int k = 0; k < QPT; ++k) t[k] = ffma2(cx[k], A.x, t[k]);
        #pragma unroll
        for (int k = 0; k < QPT; ++k) {
            float lo, hi;
            unpack2(t[k], lo, hi);
            be[k] = fminf(be[k], lo);
            bo[k] = fminf(bo[k], hi);
        }
    }

    // write per-(query, split) partial min with a^2 folded in
    float* g = (float*)g_pm4;
    const int dirb = dir * NB + b;
    #pragma unroll
    for (int k = 0; k < QPT; ++k)
        g[(dirb * NPTS + qi[k]) * 4 + split] = a2[k] + fminf(be[k], bo[k]);
}

__global__ __launch_bounds__(256) void chamfer_finalize1(void)
{
    __shared__ float red[8];
    const int t = blockIdx.x * 256 + threadIdx.x;   // 16384 threads
    float s = 0.0f;
    #pragma unroll
    for (int k = 0; k < NQSLOT / 16384; ++k) {
        const float4 v = g_pm4[t + k * 16384];
        s += fminf(fminf(v.x, v.y), fminf(v.z, v.w));
    }
    #pragma unroll
    for (int o = 16; o > 0; o >>= 1)
        s += __shfl_down_sync(0xffffffffu, s, o);
    if ((threadIdx.x & 31) == 0) red[threadIdx.x >> 5] = s;
    __syncthreads();
    if (threadIdx.x < 8) {
        s = red[threadIdx.x];
        #pragma unroll
        for (int o = 4; o > 0; o >>= 1)
            s += __shfl_down_sync(0xffu, s, o);
        if (threadIdx.x == 0) g_part[blockIdx.x] = s;
    }
}

__global__ void chamfer_finalize2(float* __restrict__ out)
{
    __shared__ float red[2];
    float v = g_part[threadIdx.x];   // 64 threads
    #pragma unroll
    for (int o = 16; o > 0; o >>= 1)
        v += __shfl_down_sync(0xffffffffu, v, o);
    if ((threadIdx.x & 31) == 0) red[threadIdx.x >> 5] = v;
    __syncthreads();
    if (threadIdx.x == 0)
        out[0] = (red[0] + red[1]) * (1.0f / (float)(NB * NPTS));
}

extern "C" void kernel_launch(void* const* d_in, const int* in_sizes, int n_in,
                              void* d_out, int out_size)
{
    const float* p1 = (const float*)d_in[0];
    const float* p2 = (const float*)d_in[1];
    float* out = (float*)d_out;

    dim3 grid(CHUNKS, NB, 2 * NSPLIT);   // 8 x 4 x 8 = 256 blocks
    chamfer_min_kernel<<<grid, TPB>>>(p1, p2);
    chamfer_finalize1<<<F1BLK, 256>>>();
    chamfer_finalize2<<<1, F1BLK>>>(out);
}

// round 6
// speedup vs baseline: 1.8859x; 1.0463x over previous
#include <cuda_runtime.h>

// ChamferLoss: B=4, N=M=8192, D=3
// dist(a,b) = a^2 + (b^2 - 2 a.b); min_b distributes over constant a^2.
// f32x2 packed FFMA, 4 queries/thread, candidates split 16-ways across blocks.

#define TPB    256
#define QPT    4
#define NPTS   8192
#define NB     4
#define NSPLIT 16
#define CANDS  (NPTS / NSPLIT)      // 512 candidates per block
#define PAIRS  (CANDS / 2)          // 256
#define QPB    (TPB * QPT)          // 1024 queries per block
#define CHUNKS (NPTS / QPB)         // 8
#define NDIRB  (2 * NB)             // 8
#define NSLOT  (NDIRB * NPTS)       // 65536 (dirb, q) slots
#define F1BLK  64

// g_pm[split][dirb][query] : partial min for that candidate split (a^2 folded in)
__device__ float g_pm[NSPLIT][NSLOT];
__device__ float g_part[F1BLK];

typedef unsigned long long u64;

__device__ __forceinline__ u64 ffma2(u64 a, u64 b, u64 c) {
    u64 d;
    asm("fma.rn.f32x2 %0, %1, %2, %3;" : "=l"(d) : "l"(a), "l"(b), "l"(c));
    return d;
}
__device__ __forceinline__ u64 pack2(float lo, float hi) {
    u64 d;
    asm("mov.b64 %0, {%1, %2};" : "=l"(d) : "f"(lo), "f"(hi));
    return d;
}
__device__ __forceinline__ void unpack2(u64 v, float& lo, float& hi) {
    asm("mov.b64 {%0, %1}, %2;" : "=f"(lo), "=f"(hi) : "l"(v));
}

__global__ __launch_bounds__(TPB, 4) void chamfer_min_kernel(
    const float* __restrict__ p1, const float* __restrict__ p2)
{
    const int dir   = blockIdx.z & 1;       // 0: p1->p2, 1: p2->p1
    const int split = blockIdx.z >> 1;      // candidate 1/16th
    const int b     = blockIdx.y;
    const float* __restrict__ q = (dir == 0) ? p1 : p2;
    const float* __restrict__ d = (dir == 0) ? p2 : p1;
    q += (size_t)b * NPTS * 3;
    d += (size_t)b * NPTS * 3 + (size_t)split * CANDS * 3;

    const int qbase = blockIdx.x * QPB;

    // pair-interleaved packed tiles:
    //  sA[j] = (x_{2j}|x_{2j+1}, y_{2j}|y_{2j+1})
    //  sB[j] = (z_{2j}|z_{2j+1}, b2_{2j}|b2_{2j+1})
    __shared__ ulonglong2 sA[PAIRS];
    __shared__ ulonglong2 sB[PAIRS];

    // one pair per thread (PAIRS == TPB)
    {
        const int p = threadIdx.x;
        const float* src = d + 6 * p;                  // 6 floats, 8B aligned
        const float2 f0 = *(const float2*)(src + 0);   // x0 y0
        const float2 f1 = *(const float2*)(src + 2);   // z0 x1
        const float2 f2 = *(const float2*)(src + 4);   // y1 z1
        const float w0 = f0.x * f0.x + f0.y * f0.y + f1.x * f1.x;
        const float w1 = f1.y * f1.y + f2.x * f2.x + f2.y * f2.y;
        sA[p] = make_ulonglong2(pack2(f0.x, f1.y), pack2(f0.y, f2.x));
        sB[p] = make_ulonglong2(pack2(f1.x, f2.y), pack2(w0, w1));
    }

    // 4 query points per thread
    float a2[QPT];
    u64   cx[QPT], cy[QPT], cz[QPT];
    #pragma unroll
    for (int k = 0; k < QPT; ++k) {
        const int i = qbase + k * TPB + threadIdx.x;
        const float ax = q[3 * i + 0], ay = q[3 * i + 1], az = q[3 * i + 2];
        a2[k] = ax * ax + ay * ay + az * az;
        cx[k] = pack2(-2.0f * ax, -2.0f * ax);
        cy[k] = pack2(-2.0f * ay, -2.0f * ay);
        cz[k] = pack2(-2.0f * az, -2.0f * az);
    }
    __syncthreads();

    float be[QPT], bo[QPT];
    #pragma unroll
    for (int k = 0; k < QPT; ++k) { be[k] = 3.4e38f; bo[k] = 3.4e38f; }

    #pragma unroll 4
    for (int j = 0; j < PAIRS; ++j) {
        const ulonglong2 A  = sA[j];    // (xx, yy)
        const ulonglong2 Bv = sB[j];    // (zz, ww)
        u64 t[QPT];
        #pragma unroll
        for (int k = 0; k < QPT; ++k) t[k] = ffma2(cz[k], Bv.x, Bv.y);
        #pragma unroll
        for (int k = 0; k < QPT; ++k) t[k] = ffma2(cy[k], A.y, t[k]);
        #pragma unroll
        for (int k = 0; k < QPT; ++k) t[k] = ffma2(cx[k], A.x, t[k]);
        #pragma unroll
        for (int k = 0; k < QPT; ++k) {
            float lo, hi;
            unpack2(t[k], lo, hi);
            be[k] = fminf(be[k], lo);
            bo[k] = fminf(bo[k], hi);
        }
    }

    // coalesced store of per-(split, dirb, query) partial mins
    const int dirb = dir * NB + b;
    float* dst = &g_pm[split][dirb * NPTS + qbase];
    #pragma unroll
    for (int k = 0; k < QPT; ++k)
        dst[k * TPB + threadIdx.x] = a2[k] + fminf(be[k], bo[k]);
}

__global__ __launch_bounds__(256) void chamfer_finalize1(void)
{
    __shared__ float red[8];
    const int t = blockIdx.x * 256 + threadIdx.x;   // 16384 threads
    float s = 0.0f;
    #pragma unroll
    for (int r = 0; r < NSLOT / 16384; ++r) {       // 4 slots per thread
        const int f = t + r * 16384;
        float m = g_pm[0][f];
        #pragma unroll
        for (int sp = 1; sp < NSPLIT; ++sp)
            m = fminf(m, g_pm[sp][f]);
        s += m;
    }
    #pragma unroll
    for (int o = 16; o > 0; o >>= 1)
        s += __shfl_down_sync(0xffffffffu, s, o);
    if ((threadIdx.x & 31) == 0) red[threadIdx.x >> 5] = s;
    __syncthreads();
    if (threadIdx.x < 8) {
        s = red[threadIdx.x];
        #pragma unroll
        for (int o = 4; o > 0; o >>= 1)
            s += __shfl_down_sync(0xffu, s, o);
        if (threadIdx.x == 0) g_part[blockIdx.x] = s;
    }
}

__global__ void chamfer_finalize2(float* __restrict__ out)
{
    __shared__ float red[2];
    float v = g_part[threadIdx.x];   // 64 threads
    #pragma unroll
    for (int o = 16; o > 0; o >>= 1)
        v += __shfl_down_sync(0xffffffffu, v, o);
    if ((threadIdx.x & 31) == 0) red[threadIdx.x >> 5] = v;
    __syncthreads();
    if (threadIdx.x == 0)
        out[0] = (red[0] + red[1]) * (1.0f / (float)(NB * NPTS));
}

extern "C" void kernel_launch(void* const* d_in, const int* in_sizes, int n_in,
                              void* d_out, int out_size)
{
    const float* p1 = (const float*)d_in[0];
    const float* p2 = (const float*)d_in[1];
    float* out = (float*)d_out;

    dim3 grid(CHUNKS, NB, 2 * NSPLIT);   // 8 x 4 x 32 = 1024 blocks
    chamfer_min_kernel<<<grid, TPB>>>(p1, p2);
    chamfer_finalize1<<<F1BLK, 256>>>();
    chamfer_finalize2<<<1, F1BLK>>>(out);
}

// round 8
// speedup vs baseline: 1.9501x; 1.0340x over previous
#include <cuda_runtime.h>

// ChamferLoss: B=4, N=M=8192, D=3
// dist(a,b) = a^2 + (b^2 - 2 a.b); min_b distributes over constant a^2.
// f32x2 packed FFMA, 8 queries/thread (amortizes smem crossbar bytes),
// candidates split 16-ways across blocks.

#define TPB    128
#define QPT    8
#define NPTS   8192
#define NB     4
#define NSPLIT 16
#define CANDS  (NPTS / NSPLIT)      // 512 candidates per block
#define PAIRS  (CANDS / 2)          // 256
#define QPB    (TPB * QPT)          // 1024 queries per block
#define CHUNKS (NPTS / QPB)         // 8
#define NDIRB  (2 * NB)             // 8
#define NSLOT  (NDIRB * NPTS)       // 65536 (dirb, q) slots
#define F1BLK  64

// g_pm[split][dirb*NPTS + query] : partial min for that candidate split (a^2 folded in)
__device__ float g_pm[NSPLIT][NSLOT];
__device__ float g_part[F1BLK];

typedef unsigned long long u64;

__device__ __forceinline__ u64 ffma2(u64 a, u64 b, u64 c) {
    u64 d;
    asm("fma.rn.f32x2 %0, %1, %2, %3;" : "=l"(d) : "l"(a), "l"(b), "l"(c));
    return d;
}
__device__ __forceinline__ u64 pack2(float lo, float hi) {
    u64 d;
    asm("mov.b64 %0, {%1, %2};" : "=l"(d) : "f"(lo), "f"(hi));
    return d;
}
__device__ __forceinline__ void unpack2(u64 v, float& lo, float& hi) {
    asm("mov.b64 {%0, %1}, %2;" : "=f"(lo), "=f"(hi) : "l"(v));
}

__global__ __launch_bounds__(TPB, 4) void chamfer_min_kernel(
    const float* __restrict__ p1, const float* __restrict__ p2)
{
    const int dir   = blockIdx.z & 1;       // 0: p1->p2, 1: p2->p1
    const int split = blockIdx.z >> 1;      // candidate 1/16th
    const int b     = blockIdx.y;
    const float* __restrict__ q = (dir == 0) ? p1 : p2;
    const float* __restrict__ d = (dir == 0) ? p2 : p1;
    q += (size_t)b * NPTS * 3;
    d += (size_t)b * NPTS * 3 + (size_t)split * CANDS * 3;

    const int qbase = blockIdx.x * QPB;

    // pair-interleaved packed tiles:
    //  sA[j] = (x_{2j}|x_{2j+1}, y_{2j}|y_{2j+1})
    //  sB[j] = (z_{2j}|z_{2j+1}, b2_{2j}|b2_{2j+1})
    __shared__ ulonglong2 sA[PAIRS];
    __shared__ ulonglong2 sB[PAIRS];

    // two pairs per thread (PAIRS == 2*TPB)
    #pragma unroll
    for (int r = 0; r < 2; ++r) {
        const int p = r * TPB + threadIdx.x;
        const float* src = d + 6 * p;                  // 6 floats, 8B aligned
        const float2 f0 = *(const float2*)(src + 0);   // x0 y0
        const float2 f1 = *(const float2*)(src + 2);   // z0 x1
        const float2 f2 = *(const float2*)(src + 4);   // y1 z1
        const float w0 = f0.x * f0.x + f0.y * f0.y + f1.x * f1.x;
        const float w1 = f1.y * f1.y + f2.x * f2.x + f2.y * f2.y;
        sA[p] = make_ulonglong2(pack2(f0.x, f1.y), pack2(f0.y, f2.x));
        sB[p] = make_ulonglong2(pack2(f1.x, f2.y), pack2(w0, w1));
    }

    // 8 query points per thread
    float a2[QPT];
    u64   cx[QPT], cy[QPT], cz[QPT];
    #pragma unroll
    for (int k = 0; k < QPT; ++k) {
        const int i = qbase + k * TPB + threadIdx.x;
        const float ax = q[3 * i + 0], ay = q[3 * i + 1], az = q[3 * i + 2];
        a2[k] = ax * ax + ay * ay + az * az;
        cx[k] = pack2(-2.0f * ax, -2.0f * ax);
        cy[k] = pack2(-2.0f * ay, -2.0f * ay);
        cz[k] = pack2(-2.0f * az, -2.0f * az);
    }
    __syncthreads();

    float be[QPT], bo[QPT];
    #pragma unroll
    for (int k = 0; k < QPT; ++k) { be[k] = 3.4e38f; bo[k] = 3.4e38f; }

    #pragma unroll 2
    for (int j = 0; j < PAIRS; ++j) {
        const ulonglong2 A  = sA[j];    // (xx, yy)
        const ulonglong2 Bv = sB[j];    // (zz, ww)
        u64 t[QPT];
        #pragma unroll
        for (int k = 0; k < QPT; ++k) t[k] = ffma2(cz[k], Bv.x, Bv.y);
        #pragma unroll
        for (int k = 0; k < QPT; ++k) t[k] = ffma2(cy[k], A.y, t[k]);
        #pragma unroll
        for (int k = 0; k < QPT; ++k) t[k] = ffma2(cx[k], A.x, t[k]);
        #pragma unroll
        for (int k = 0; k < QPT; ++k) {
            float lo, hi;
            unpack2(t[k], lo, hi);
            be[k] = fminf(be[k], lo);
            bo[k] = fminf(bo[k], hi);
        }
    }

    // coalesced store of per-(split, dirb, query) partial mins
    const int dirb = dir * NB + b;
    float* dst = &g_pm[split][dirb * NPTS + qbase];
    #pragma unroll
    for (int k = 0; k < QPT; ++k)
        dst[k * TPB + threadIdx.x] = a2[k] + fminf(be[k], bo[k]);
}

__global__ __launch_bounds__(256) void chamfer_finalize1(void)
{
    __shared__ float red[8];
    const int t = blockIdx.x * 256 + threadIdx.x;   // 16384 threads
    float s = 0.0f;
    #pragma unroll
    for (int r = 0; r < NSLOT / 16384; ++r) {       // 4 slots per thread
        const int f = t + r * 16384;
        float m = g_pm[0][f];
        #pragma unroll
        for (int sp = 1; sp < NSPLIT; ++sp)
            m = fminf(m, g_pm[sp][f]);
        s += m;
    }
    #pragma unroll
    for (int o = 16; o > 0; o >>= 1)
        s += __shfl_down_sync(0xffffffffu, s, o);
    if ((threadIdx.x & 31) == 0) red[threadIdx.x >> 5] = s;
    __syncthreads();
    if (threadIdx.x < 8) {
        s = red[threadIdx.x];
        #pragma unroll
        for (int o = 4; o > 0; o >>= 1)
            s += __shfl_down_sync(0xffu, s, o);
        if (threadIdx.x == 0) g_part[blockIdx.x] = s;
    }
}

__global__ void chamfer_finalize2(float* __restrict__ out)
{
    __shared__ float red[2];
    float v = g_part[threadIdx.x];   // 64 threads
    #pragma unroll
    for (int o = 16; o > 0; o >>= 1)
        v += __shfl_down_sync(0xffffffffu, v, o);
    if ((threadIdx.x & 31) == 0) red[threadIdx.x >> 5] = v;
    __syncthreads();
    if (threadIdx.x == 0)
        out[0] = (red[0] + red[1]) * (1.0f / (float)(NB * NPTS));
}

extern "C" void kernel_launch(void* const* d_in, const int* in_sizes, int n_in,
                              void* d_out, int out_size)
{
    const float* p1 = (const float*)d_in[0];
    const float* p2 = (const float*)d_in[1];
    float* out = (float*)d_out;

    dim3 grid(CHUNKS, NB, 2 * NSPLIT);   // 8 x 4 x 32 = 1024 blocks
    chamfer_min_kernel<<<grid, TPB>>>(p1, p2);
    chamfer_finalize1<<<F1BLK, 256>>>();
    chamfer_finalize2<<<1, F1BLK>>>(out);
}

// round 10
// speedup vs baseline: 2.3423x; 1.2011x over previous
#include <cuda_runtime.h>

// ChamferLoss: B=4, N=M=8192, D=3
// Fused symmetric tiles: each block computes dist tile (1024 p1-queries x 256
// p2-candidates) ONCE; produces row-min partials (p1->p2) and col-min partials
// (p2->p1). d = a^2 + b^2 - 2 a.b via f32x2 packed FMA (a^2 folded in, needed
// for col mins). Col mins via per-warp rotation (race-free, no atomics).

#define TPB     128
#define QPT     8
#define NPTS    8192
#define NB      4
#define QPB     (TPB * QPT)         // 1024 queries per block
#define QCH     (NPTS / QPB)        // 8 query chunks
#define CCH     32                  // candidate chunks
#define CANDS   (NPTS / CCH)        // 256 candidates per block
#define PAIRS   (CANDS / 2)         // 128 == TPB
#define NSLOT   (NB * NPTS)         // 32768 (b, point) slots
#define F1BLK   64

__device__ float g_row[CCH][NSLOT];   // row-min partial per candidate-chunk
__device__ float g_col[QCH][NSLOT];   // col-min partial per query-chunk
__device__ float g_part[F1BLK];

typedef unsigned long long u64;

__device__ __forceinline__ u64 ffma2(u64 a, u64 b, u64 c) {
    u64 d;
    asm("fma.rn.f32x2 %0, %1, %2, %3;" : "=l"(d) : "l"(a), "l"(b), "l"(c));
    return d;
}
__device__ __forceinline__ u64 fadd2(u64 a, u64 b) {
    u64 d;
    asm("add.rn.f32x2 %0, %1, %2;" : "=l"(d) : "l"(a), "l"(b));
    return d;
}
__device__ __forceinline__ u64 pack2(float lo, float hi) {
    u64 d;
    asm("mov.b64 %0, {%1, %2};" : "=l"(d) : "f"(lo), "f"(hi));
    return d;
}
__device__ __forceinline__ void unpack2(u64 v, float& lo, float& hi) {
    asm("mov.b64 {%0, %1}, %2;" : "=f"(lo), "=f"(hi) : "l"(v));
}

__global__ __launch_bounds__(TPB) void chamfer_tile_kernel(
    const float* __restrict__ p1, const float* __restrict__ p2)
{
    const int qc = blockIdx.x;            // query chunk (8)
    const int b  = blockIdx.y;            // batch (4)
    const int cc = blockIdx.z;            // candidate chunk (32)
    const float* __restrict__ q = p1 + (size_t)b * NPTS * 3;
    const float* __restrict__ d = p2 + (size_t)b * NPTS * 3 + (size_t)cc * CANDS * 3;

    const int tid  = threadIdx.x;
    const int lane = tid & 31;
    const int w    = tid >> 5;
    const int qbase = qc * QPB;
    const int cbase = cc * CANDS;

    // candidate tile, pair-interleaved packed:
    //  sA[j] = (x_{2j}|x_{2j+1}, y_{2j}|y_{2j+1})
    //  sB[j] = (z_{2j}|z_{2j+1}, b2_{2j}|b2_{2j+1})
    __shared__ ulonglong2 sA[PAIRS];
    __shared__ ulonglong2 sB[PAIRS];
    __shared__ float col_lo[4][PAIRS];    // per-warp col mins (even candidate)
    __shared__ float col_hi[4][PAIRS];    // per-warp col mins (odd candidate)

    {   // one pair per thread (PAIRS == TPB)
        const float* src = d + 6 * tid;
        const float2 f0 = *(const float2*)(src + 0);   // x0 y0
        const float2 f1 = *(const float2*)(src + 2);   // z0 x1
        const float2 f2 = *(const float2*)(src + 4);   // y1 z1
        const float w0 = f0.x * f0.x + f0.y * f0.y + f1.x * f1.x;
        const float w1 = f1.y * f1.y + f2.x * f2.x + f2.y * f2.y;
        sA[tid] = make_ulonglong2(pack2(f0.x, f1.y), pack2(f0.y, f2.x));
        sB[tid] = make_ulonglong2(pack2(f1.x, f2.y), pack2(w0, w1));
    }
    #pragma unroll
    for (int ww = 0; ww < 4; ++ww) {
        col_lo[ww][tid] = 3.4e38f;
        col_hi[ww][tid] = 3.4e38f;
    }

    // 8 query points per thread; coeffs packed (duplicated halves)
    u64 cx[QPT], cy[QPT], cz[QPT], a2p[QPT];
    #pragma unroll
    for (int k = 0; k < QPT; ++k) {
        const int i = qbase + k * TPB + tid;
        const float ax = q[3 * i + 0], ay = q[3 * i + 1], az = q[3 * i + 2];
        const float a2 = ax * ax + ay * ay + az * az;
        cx[k] = pack2(-2.0f * ax, -2.0f * ax);
        cy[k] = pack2(-2.0f * ay, -2.0f * ay);
        cz[k] = pack2(-2.0f * az, -2.0f * az);
        a2p[k] = pack2(a2, a2);
    }
    __syncthreads();

    float be[QPT], bo[QPT];
    #pragma unroll
    for (int k = 0; k < QPT; ++k) { be[k] = 3.4e38f; bo[k] = 3.4e38f; }

    // rotation: at round r, lane l handles pair (l+r)&127 -> within a warp all
    // lanes hit distinct pairs, so per-warp col RMW is race-free without sync.
    #pragma unroll 2
    for (int r = 0; r < PAIRS; ++r) {
        const int j = (lane + r) & (PAIRS - 1);
        const ulonglong2 A  = sA[j];    // (xx, yy)
        const ulonglong2 Bv = sB[j];    // (zz, ww)

        u64 dd[QPT];
        #pragma unroll
        for (int k = 0; k < QPT; ++k) dd[k] = ffma2(cz[k], Bv.x, Bv.y);
        #pragma unroll
        for (int k = 0; k < QPT; ++k) dd[k] = ffma2(cy[k], A.y, dd[k]);
        #pragma unroll
        for (int k = 0; k < QPT; ++k) dd[k] = ffma2(cx[k], A.x, dd[k]);
        #pragma unroll
        for (int k = 0; k < QPT; ++k) dd[k] = fadd2(dd[k], a2p[k]);  // full dist

        // row mins (per query) + gather scalars for col tree
        float lo[QPT], hi[QPT];
        #pragma unroll
        for (int k = 0; k < QPT; ++k) {
            unpack2(dd[k], lo[k], hi[k]);
            be[k] = fminf(be[k], lo[k]);
            bo[k] = fminf(bo[k], hi[k]);
        }
        // col mins: tree over this thread's 8 queries
        float cE = fminf(fminf(fminf(lo[0], lo[1]), fminf(lo[2], lo[3])),
                         fminf(fminf(lo[4], lo[5]), fminf(lo[6], lo[7])));
        float cO = fminf(fminf(fminf(hi[0], hi[1]), fminf(hi[2], hi[3])),
                         fminf(fminf(hi[4], hi[5]), fminf(hi[6], hi[7])));
        col_lo[w][j] = fminf(col_lo[w][j], cE);
        col_hi[w][j] = fminf(col_hi[w][j], cO);
    }

    // row partials (dist already includes a^2)
    {
        float* dst = &g_row[cc][b * NPTS + qbase];
        #pragma unroll
        for (int k = 0; k < QPT; ++k)
            dst[k * TPB + tid] = fminf(be[k], bo[k]);
    }

    // col partials: combine 4 warp copies
    __syncthreads();
    {
        const int p = tid;   // PAIRS == TPB
        const float mE = fminf(fminf(col_lo[0][p], col_lo[1][p]),
                               fminf(col_lo[2][p], col_lo[3][p]));
        const float mO = fminf(fminf(col_hi[0][p], col_hi[1][p]),
                               fminf(col_hi[2][p], col_hi[3][p]));
        float* dst = &g_col[qc][b * NPTS + cbase];
        dst[2 * p + 0] = mE;
        dst[2 * p + 1] = mO;
    }
}

__global__ __launch_bounds__(256) void chamfer_finalize1(void)
{
    __shared__ float red[8];
    const int t = blockIdx.x * 256 + threadIdx.x;   // 16384 threads
    float s = 0.0f;
    #pragma unroll
    for (int r = 0; r < NSLOT / 16384; ++r) {       // 2 row + 2 col slots/thread
        const int f = t + r * 16384;
        float m = g_row[0][f];
        #pragma unroll
        for (int c = 1; c < CCH; ++c) m = fminf(m, g_row[c][f]);
        s += m;
        float m2 = g_col[0][f];
        #pragma unroll
        for (int c = 1; c < QCH; ++c) m2 = fminf(m2, g_col[c][f]);
        s += m2;
    }
    #pragma unroll
    for (int o = 16; o > 0; o >>= 1)
        s += __shfl_down_sync(0xffffffffu, s, o);
    if ((threadIdx.x & 31) == 0) red[threadIdx.x >> 5] = s;
    __syncthreads();
    if (threadIdx.x < 8) {
        s = red[threadIdx.x];
        #pragma unroll
        for (int o = 4; o > 0; o >>= 1)
            s += __shfl_down_sync(0xffu, s, o);
        if (threadIdx.x == 0) g_part[blockIdx.x] = s;
    }
}

__global__ void chamfer_finalize2(float* __restrict__ out)
{
    __shared__ float red[2];
    float v = g_part[threadIdx.x];   // 64 threads
    #pragma unroll
    for (int o = 16; o > 0; o >>= 1)
        v += __shfl_down_sync(0xffffffffu, v, o);
    if ((threadIdx.x & 31) == 0) red[threadIdx.x >> 5] = v;
    __syncthreads();
    if (threadIdx.x == 0)
        out[0] = (red[0] + red[1]) * (1.0f / (float)(NB * NPTS));
}

extern "C" void kernel_launch(void* const* d_in, const int* in_sizes, int n_in,
                              void* d_out, int out_size)
{
    const float* p1 = (const float*)d_in[0];
    const float* p2 = (const float*)d_in[1];
    float* out = (float*)d_out;

    dim3 grid(QCH, NB, CCH);   // 8 x 4 x 32 = 1024 blocks
    chamfer_tile_kernel<<<grid, TPB>>>(p1, p2);
    chamfer_finalize1<<<F1BLK, 256>>>();
    chamfer_finalize2<<<1, F1BLK>>>(out);
}